// round 8
// baseline (speedup 1.0000x reference)
#include <cuda_runtime.h>
#include <cuda_bf16.h>

// ---------------------------------------------------------------------------
// CNN_22952305230196: conv(3->4,3x3,SAME)+relu+avgpool2 -> conv(4->16)+relu+
// avgpool2 -> NetVLAD (K=4, D=16) -> intra L2 norm -> global L2 norm -> 64x7.
// N=32, input 512x512. Output (32,7) float32.
//
// All heavy math uses packed f32x2 (PTX fma/add.rn.f32x2 -> dual-rate SASS
// packed ops). Weights duplicated (w,w) in shared -> packed broadcast via one
// LDS.64. conv1 processes 2 adjacent pooled pixels/thread (shared input pairs,
// LDG.128 row loads, one weight LDS feeds 4 FMA2s). NetVLAD fused into
// conv2's epilogue; 4 px/thread, 34 packed register accumulators, one
// butterfly reduction per thread; conv2 loop is channel-outer to cap regs.
// ---------------------------------------------------------------------------

#define NIMG 32

typedef unsigned long long u64t;

#define FMA2(acc, a, b) \
    asm("fma.rn.f32x2 %0, %1, %2, %0;" : "+l"(acc) : "l"(a), "l"(b))
#define ADD2(acc, a) \
    asm("add.rn.f32x2 %0, %0, %1;" : "+l"(acc) : "l"(a))
#define PACK2(d, lo, hi) \
    asm("mov.b64 %0, {%1, %2};" : "=l"(d) : "f"(lo), "f"(hi))
#define UNPACK2(lo, hi, s) \
    asm("mov.b64 {%0, %1}, %2;" : "=f"(lo), "=f"(hi) : "l"(s))

// scratch (allowed: __device__ globals, no allocation)
__device__ float g_h1[NIMG * 4 * 256 * 256];    // 33.5 MB
__device__ u64t  g_vpart[NIMG * 16 * 34];       // [n][chunk] 34 packed pairs

// ---------------------------------------------------------------------------
// Kernel 1: conv1 (3->4, 3x3 SAME) + relu + 2x2 avgpool. One thread = TWO
// adjacent pooled pixels (py, 2qx) and (py, 2qx+1): input rows loaded as one
// aligned float4 + 2 edge floats, 5 shared packed pairs per row; each weight
// LDS.64 feeds 4 FMA2s. grid: 32*256*128/256 = 4096 blocks x 256 threads.
// ---------------------------------------------------------------------------
__global__ void __launch_bounds__(256) k_conv1(
    const float* __restrict__ x, const float* __restrict__ w,
    const float* __restrict__ b)
{
    __shared__ float2 s_wd[108];  // (4,3,3,3) duplicated
    __shared__ float2 s_bd[4];
    int t = threadIdx.x;
    if (t < 108) { float v = w[t]; s_wd[t] = make_float2(v, v); }
    if (t < 4)   { float v = b[t]; s_bd[t] = make_float2(v, v); }
    __syncthreads();

    int idx = blockIdx.x * 256 + t;
    int qx = idx & 127;           // pixel-pair index: pixels 2qx, 2qx+1
    int py = (idx >> 7) & 255;
    int n  = idx >> 15;

    int y0 = 2 * py - 1;          // top input row (may be -1)
    int xb = 4 * qx;              // 16B-aligned input column of the float4
    bool left  = (qx > 0);        // xb-1 valid
    bool right = (qx < 127);      // xb+4 valid

    // packed pairs per row: p[j] = (in[xb-1+j], in[xb+j]), j=0..4.
    // pixel A (out 2qx) uses p[0..2]; pixel B (out 2qx+1) uses p[2..4].
    u64t pr[3][4][5];
#pragma unroll
    for (int c = 0; c < 3; c++) {
        const float* xp = x + ((size_t)(n * 3 + c) << 18);  // *512*512
#pragma unroll
        for (int r = 0; r < 4; r++) {
            int iy = y0 + r;
            bool yok = (unsigned)iy < 512u;
            const float* rp = xp + iy * 512;
            float4 f = yok ? __ldg((const float4*)(rp + xb))
                           : make_float4(0.f, 0.f, 0.f, 0.f);
            float vm1 = (yok && left)  ? __ldg(rp + xb - 1) : 0.0f;
            float vp4 = (yok && right) ? __ldg(rp + xb + 4) : 0.0f;
            PACK2(pr[c][r][0], vm1, f.x);
            PACK2(pr[c][r][1], f.x, f.y);
            PACK2(pr[c][r][2], f.y, f.z);
            PACK2(pr[c][r][3], f.z, f.w);
            PACK2(pr[c][r][4], f.w, vp4);
        }
    }

#pragma unroll
    for (int oc = 0; oc < 4; oc++) {
        u64t bias = *(const u64t*)&s_bd[oc];
        u64t aTA = bias, aBA = bias;   // pixel A: (a00,a01), (a10,a11)
        u64t aTB = bias, aBB = bias;   // pixel B
#pragma unroll
        for (int c = 0; c < 3; c++)
#pragma unroll
            for (int ky = 0; ky < 3; ky++)
#pragma unroll
                for (int kx = 0; kx < 3; kx++) {
                    u64t wd = *(const u64t*)&s_wd[((oc * 3 + c) * 3 + ky) * 3 + kx];
                    FMA2(aTA, pr[c][ky    ][kx    ], wd);
                    FMA2(aBA, pr[c][ky + 1][kx    ], wd);
                    FMA2(aTB, pr[c][ky    ][kx + 2], wd);
                    FMA2(aBB, pr[c][ky + 1][kx + 2], wd);
                }
        float a00, a01, a10, a11, b00, b01, b10, b11;
        UNPACK2(a00, a01, aTA);
        UNPACK2(a10, a11, aBA);
        UNPACK2(b00, b01, aTB);
        UNPACK2(b10, b11, aBB);
        float rA = 0.25f * (fmaxf(a00, 0.f) + fmaxf(a01, 0.f) +
                            fmaxf(a10, 0.f) + fmaxf(a11, 0.f));
        float rB = 0.25f * (fmaxf(b00, 0.f) + fmaxf(b01, 0.f) +
                            fmaxf(b10, 0.f) + fmaxf(b11, 0.f));
        // 2qx even -> 8B-aligned float2 store
        *(float2*)&g_h1[((size_t)(n * 4 + oc) << 16) + (py << 8) + 2 * qx] =
            make_float2(rA, rB);
    }
}

// ---------------------------------------------------------------------------
// Kernel 2: conv2 (4->16) + relu + avgpool2, FUSED with NetVLAD soft-assign.
// Each thread processes 4 pooled pixels (stride 256 in a 1024-px chunk),
// FMA2-accumulating packed vlad pairs in registers; one butterfly reduction
// per thread at the end. Conv loop is channel-outer: 32 packed accumulators
// (16 oc x {top,bot}) resident, only 12 input pairs (one channel) live.
// grid: 32*16384/1024 = 512 blocks x 256 threads; n = blockIdx.x >> 4.
// ---------------------------------------------------------------------------
__global__ void __launch_bounds__(256) k_conv2_vlad(
    const float* __restrict__ w, const float* __restrict__ b,
    const float* __restrict__ aw, const float* __restrict__ ab)
{
    __shared__ float2 s_wd[576];  // (16,4,3,3) duplicated
    __shared__ float2 s_bd[16];
    __shared__ float  s_aw[64];   // assign_w (K=4, D=16)
    __shared__ float  s_ab[4];
    __shared__ u64t   s_red[8][34];
    int t = threadIdx.x;
    for (int i = t; i < 576; i += 256) { float v = w[i]; s_wd[i] = make_float2(v, v); }
    if (t < 16) { float v = b[t]; s_bd[t] = make_float2(v, v); }
    if (t < 64) s_aw[t] = aw[t];
    if (t < 4)  s_ab[t] = ab[t];
    __syncthreads();

    int n    = blockIdx.x >> 4;
    int base = (blockIdx.x & 15) * 1024;

    u64t pv[34];
#pragma unroll
    for (int i = 0; i < 34; i++) pv[i] = 0ull;

#pragma unroll 1
    for (int p = 0; p < 4; p++) {
        int pix = base + p * 256 + t;     // 0..16383 within image
        int px = pix & 127;
        int py = pix >> 7;

        int y0 = 2 * py - 1;
        int xc = 2 * px;
        bool left  = (px > 0);
        bool right = (px < 127);

        // 16 oc accumulators, top and bottom pooled rows
        u64t accT[16], accB[16];
#pragma unroll
        for (int oc = 0; oc < 16; oc++) {
            accT[oc] = *(const u64t*)&s_bd[oc];
            accB[oc] = accT[oc];
        }

        // channel-outer: only one channel's 12 packed pairs live at a time
#pragma unroll
        for (int c = 0; c < 4; c++) {
            u64t prc[4][3];
            const float* xp = g_h1 + ((size_t)(n * 4 + c) << 16);  // *256*256
#pragma unroll
            for (int r = 0; r < 4; r++) {
                int iy = y0 + r;
                bool yok = (unsigned)iy < 256u;
                const float* rp = xp + iy * 256;
                float2 m = yok ? __ldg((const float2*)(rp + xc))
                               : make_float2(0.f, 0.f);
                float v0 = (yok && left)  ? __ldg(rp + xc - 1) : 0.0f;
                float v3 = (yok && right) ? __ldg(rp + xc + 2) : 0.0f;
                PACK2(prc[r][0], v0, m.x);
                PACK2(prc[r][1], m.x, m.y);
                PACK2(prc[r][2], m.y, v3);
            }
#pragma unroll
            for (int oc = 0; oc < 16; oc++)
#pragma unroll
                for (int ky = 0; ky < 3; ky++)
#pragma unroll
                    for (int kx = 0; kx < 3; kx++) {
                        u64t wd = *(const u64t*)&s_wd[((oc * 4 + c) * 3 + ky) * 3 + kx];
                        FMA2(accT[oc], prc[ky    ][kx], wd);
                        FMA2(accB[oc], prc[ky + 1][kx], wd);
                    }
        }

        // relu + pool -> 16 channel values for this pooled pixel
        float xv[16];
#pragma unroll
        for (int oc = 0; oc < 16; oc++) {
            float a00, a01, a10, a11;
            UNPACK2(a00, a01, accT[oc]);
            UNPACK2(a10, a11, accB[oc]);
            xv[oc] = 0.25f * (fmaxf(a00, 0.f) + fmaxf(a01, 0.f) +
                              fmaxf(a10, 0.f) + fmaxf(a11, 0.f));
        }

        // NetVLAD soft-assign for this pixel
        float lg[4];
#pragma unroll
        for (int k = 0; k < 4; k++) {
            float s = s_ab[k];
#pragma unroll
            for (int c = 0; c < 16; c++) s = fmaf(xv[c], s_aw[k * 16 + c], s);
            lg[k] = s;
        }
        float mx = fmaxf(fmaxf(lg[0], lg[1]), fmaxf(lg[2], lg[3]));
        float e0 = __expf(lg[0] - mx), e1 = __expf(lg[1] - mx);
        float e2 = __expf(lg[2] - mx), e3 = __expf(lg[3] - mx);
        float inv = 1.0f / (e0 + e1 + e2 + e3);
        float av[4] = {e0 * inv, e1 * inv, e2 * inv, e3 * inv};

        // accumulate packed pairs: pv[k*8+j] += (a_k,a_k)*(xv[2j],xv[2j+1])
        u64t xq[8];
#pragma unroll
        for (int j = 0; j < 8; j++) PACK2(xq[j], xv[2 * j], xv[2 * j + 1]);
#pragma unroll
        for (int k = 0; k < 4; k++) {
            u64t ak2; PACK2(ak2, av[k], av[k]);
#pragma unroll
            for (int j = 0; j < 8; j++) FMA2(pv[k * 8 + j], ak2, xq[j]);
        }
        u64t a01p, a23p;
        PACK2(a01p, av[0], av[1]); ADD2(pv[32], a01p);
        PACK2(a23p, av[2], av[3]); ADD2(pv[33], a23p);
    }

    // packed butterfly: warp -> per-warp partial -> 8-way sum in 34 threads
    int lane = t & 31, wrp = t >> 5;
#pragma unroll
    for (int i = 0; i < 34; i++) {
        u64t v = pv[i];
#pragma unroll
        for (int o = 16; o > 0; o >>= 1) {
            u64t s = __shfl_xor_sync(0xffffffffu, v, o);
            ADD2(v, s);
        }
        if (lane == 0) s_red[wrp][i] = v;
    }
    __syncthreads();
    if (t < 34) {
        u64t s = s_red[0][t];
#pragma unroll
        for (int wq = 1; wq < 8; wq++) ADD2(s, s_red[wq][t]);
        g_vpart[blockIdx.x * 34 + t] = s;   // blockIdx.x == n*16 + chunk
    }
}

// ---------------------------------------------------------------------------
// Kernel 3: reduce 16 chunk-partials; vlad[k,c] = acc - asum[k]*cent[k,c];
// intra L2 norm over c; global L2 norm; out = vlad @ lin_w.T + lin_b.
// grid: 32 blocks x 64 threads. g_vpart pair j holds floats (2j, 2j+1):
// j<32 -> vlad[2j],vlad[2j+1]; j=32 -> asum0,asum1; j=33 -> asum2,asum3.
// ---------------------------------------------------------------------------
__global__ void __launch_bounds__(64) k_head(
    const float* __restrict__ cent, const float* __restrict__ lw,
    const float* __restrict__ lb, float* __restrict__ out)
{
    __shared__ float s_v[64];
    __shared__ float s_n[4];
    __shared__ float s_g;
    int n = blockIdx.x, t = threadIdx.x;

    const float* p = (const float*)(g_vpart + (size_t)n * 16 * 34);
    float acc = 0.f, asum = 0.f;
    int k = t >> 4;
#pragma unroll
    for (int s = 0; s < 16; s++) {
        acc  += p[s * 68 + t];
        asum += p[s * 68 + 64 + k];
    }
    float v = acc - asum * cent[t];
    s_v[t] = v;
    __syncthreads();

    if (t < 4) {
        float s = 0.f;
#pragma unroll
        for (int c = 0; c < 16; c++) { float q = s_v[t * 16 + c]; s += q * q; }
        s_n[t] = fmaxf(sqrtf(s), 1e-12f);
    }
    __syncthreads();
    v = s_v[t] / s_n[k];
    s_v[t] = v;
    __syncthreads();
    if (t == 0) {
        float s = 0.f;
#pragma unroll
        for (int i = 0; i < 64; i++) s += s_v[i] * s_v[i];
        s_g = fmaxf(sqrtf(s), 1e-12f);
    }
    __syncthreads();
    if (t < 7) {
        float ig = 1.0f / s_g;
        float s = lb[t];
#pragma unroll
        for (int i = 0; i < 64; i++) s = fmaf(s_v[i] * ig, lw[t * 64 + i], s);
        out[n * 7 + t] = s;
    }
}

// ---------------------------------------------------------------------------
extern "C" void kernel_launch(void* const* d_in, const int* in_sizes, int n_in,
                              void* d_out, int out_size)
{
    const float* x     = (const float*)d_in[0];
    const float* c1w   = (const float*)d_in[1];
    const float* c1b   = (const float*)d_in[2];
    const float* c2w   = (const float*)d_in[3];
    const float* c2b   = (const float*)d_in[4];
    const float* cent  = (const float*)d_in[5];
    const float* aw    = (const float*)d_in[6];
    const float* ab    = (const float*)d_in[7];
    const float* lw    = (const float*)d_in[8];
    const float* lb    = (const float*)d_in[9];
    float* out = (float*)d_out;

    k_conv1<<<NIMG * 256 * 128 / 256, 256>>>(x, c1w, c1b);
    k_conv2_vlad<<<NIMG * 16384 / 1024, 256>>>(c2w, c2b, aw, ab);
    k_head<<<NIMG, 64>>>(cent, lw, lb, out);
}

// round 10
// speedup vs baseline: 1.2153x; 1.2153x over previous
#include <cuda_runtime.h>
#include <cuda_bf16.h>

// ---------------------------------------------------------------------------
// CNN_22952305230196: conv(3->4,3x3,SAME)+relu+avgpool2 -> conv(4->16)+relu+
// avgpool2 -> NetVLAD (K=4, D=16) -> intra L2 norm -> global L2 norm -> 64x7.
// N=32, input 512x512. Output (32,7) float32.
//
// R8 ncu: regs=140 -> 1 block/SM (occ 12.2%), issue 36% -> latency-bound.
// R9 fix kept: both heavy kernels at <=128 regs, __launch_bounds__(256,2).
// This round: per-pixel reduction upgraded to recursive-halving butterfly
// (exchange value-set halves; lane l ends owning sum of value l) -- 62 SHFL
// + 31 ADD2 per pixel instead of 340 SHFL + ~205 ADD2.
// ---------------------------------------------------------------------------

#define NIMG 32

typedef unsigned long long u64t;

#define FMA2(acc, a, b) \
    asm("fma.rn.f32x2 %0, %1, %2, %0;" : "+l"(acc) : "l"(a), "l"(b))
#define ADD2(acc, a) \
    asm("add.rn.f32x2 %0, %0, %1;" : "+l"(acc) : "l"(a))
#define MUL2(d, a, b) \
    asm("mul.rn.f32x2 %0, %1, %2;" : "=l"(d) : "l"(a), "l"(b))
#define PACK2(d, lo, hi) \
    asm("mov.b64 %0, {%1, %2};" : "=l"(d) : "f"(lo), "f"(hi))
#define UNPACK2(lo, hi, s) \
    asm("mov.b64 {%0, %1}, %2;" : "=f"(lo), "=f"(hi) : "l"(s))

// scratch (allowed: __device__ globals, no allocation)
__device__ float g_h1[NIMG * 4 * 256 * 256];    // 33.5 MB
__device__ u64t  g_vpart[NIMG * 16 * 34];       // [n][chunk] 34 packed pairs

// ---------------------------------------------------------------------------
// Kernel 1: conv1 (3->4, 3x3 SAME) + relu + 2x2 avgpool. One thread = TWO
// adjacent pooled pixels. CHANNEL-OUTER: only one channel's 20 packed pairs
// live at a time; 16 packed accumulators resident -> ~90 regs -> 2 blocks/SM.
// grid: 32*256*128/256 = 4096 blocks x 256 threads.
// ---------------------------------------------------------------------------
__global__ void __launch_bounds__(256, 2) k_conv1(
    const float* __restrict__ x, const float* __restrict__ w,
    const float* __restrict__ b)
{
    __shared__ float2 s_wd[108];  // (4,3,3,3) duplicated
    __shared__ float2 s_bd[4];
    int t = threadIdx.x;
    if (t < 108) { float v = w[t]; s_wd[t] = make_float2(v, v); }
    if (t < 4)   { float v = b[t]; s_bd[t] = make_float2(v, v); }
    __syncthreads();

    int idx = blockIdx.x * 256 + t;
    int qx = idx & 127;           // pixel-pair index: pixels 2qx, 2qx+1
    int py = (idx >> 7) & 255;
    int n  = idx >> 15;

    int y0 = 2 * py - 1;          // top input row (may be -1)
    int xb = 4 * qx;              // 16B-aligned input column of the float4
    bool left  = (qx > 0);
    bool right = (qx < 127);

    // acc[oc][0]=A-top, [1]=A-bot, [2]=B-top, [3]=B-bot (packed pooled pairs)
    u64t acc[4][4];
#pragma unroll
    for (int oc = 0; oc < 4; oc++) {
        u64t bias = *(const u64t*)&s_bd[oc];
        acc[oc][0] = bias; acc[oc][1] = bias;
        acc[oc][2] = bias; acc[oc][3] = bias;
    }

#pragma unroll
    for (int c = 0; c < 3; c++) {
        // pairs p[j] = (in[xb-1+j], in[xb+j]), j=0..4; A uses 0..2, B 2..4
        u64t prc[4][5];
        const float* xp = x + ((size_t)(n * 3 + c) << 18);  // *512*512
#pragma unroll
        for (int r = 0; r < 4; r++) {
            int iy = y0 + r;
            bool yok = (unsigned)iy < 512u;
            const float* rp = xp + iy * 512;
            float4 f = yok ? __ldg((const float4*)(rp + xb))
                           : make_float4(0.f, 0.f, 0.f, 0.f);
            float vm1 = (yok && left)  ? __ldg(rp + xb - 1) : 0.0f;
            float vp4 = (yok && right) ? __ldg(rp + xb + 4) : 0.0f;
            PACK2(prc[r][0], vm1, f.x);
            PACK2(prc[r][1], f.x, f.y);
            PACK2(prc[r][2], f.y, f.z);
            PACK2(prc[r][3], f.z, f.w);
            PACK2(prc[r][4], f.w, vp4);
        }
#pragma unroll
        for (int oc = 0; oc < 4; oc++)
#pragma unroll
            for (int ky = 0; ky < 3; ky++)
#pragma unroll
                for (int kx = 0; kx < 3; kx++) {
                    u64t wd = *(const u64t*)&s_wd[((oc * 3 + c) * 3 + ky) * 3 + kx];
                    FMA2(acc[oc][0], prc[ky    ][kx    ], wd);
                    FMA2(acc[oc][1], prc[ky + 1][kx    ], wd);
                    FMA2(acc[oc][2], prc[ky    ][kx + 2], wd);
                    FMA2(acc[oc][3], prc[ky + 1][kx + 2], wd);
                }
    }

#pragma unroll
    for (int oc = 0; oc < 4; oc++) {
        float a00, a01, a10, a11, b00, b01, b10, b11;
        UNPACK2(a00, a01, acc[oc][0]);
        UNPACK2(a10, a11, acc[oc][1]);
        UNPACK2(b00, b01, acc[oc][2]);
        UNPACK2(b10, b11, acc[oc][3]);
        float rA = 0.25f * (fmaxf(a00, 0.f) + fmaxf(a01, 0.f) +
                            fmaxf(a10, 0.f) + fmaxf(a11, 0.f));
        float rB = 0.25f * (fmaxf(b00, 0.f) + fmaxf(b01, 0.f) +
                            fmaxf(b10, 0.f) + fmaxf(b11, 0.f));
        *(float2*)&g_h1[((size_t)(n * 4 + oc) << 16) + (py << 8) + 2 * qx] =
            make_float2(rA, rB);
    }
}

// ---------------------------------------------------------------------------
// Kernel 2: conv2 (4->16) + relu + avgpool2 FUSED with NetVLAD soft-assign.
// 4 px/thread. Conv in TWO 8-oc sweeps over channels (32-reg acc set; g_h1
// re-read is L2-hot). Per-pixel recursive-halving butterfly: lanes exchange
// halves of their 32-value set; after 5 levels lane l owns the warp-sum of
// value l (asum pair reduced by plain allreduce). ~110 regs -> 2 blocks/SM.
// grid: 32*16384/1024 = 512 blocks x 256 threads; n = blockIdx.x >> 4.
// ---------------------------------------------------------------------------
__global__ void __launch_bounds__(256, 2) k_conv2_vlad(
    const float* __restrict__ w, const float* __restrict__ b,
    const float* __restrict__ aw, const float* __restrict__ ab)
{
    __shared__ float2 s_wd[576];  // (16,4,3,3) duplicated
    __shared__ float2 s_bd[16];
    __shared__ float  s_aw[64];   // assign_w (K=4, D=16)
    __shared__ float  s_ab[4];
    __shared__ u64t   s_red[8][34];
    int t = threadIdx.x;
    for (int i = t; i < 576; i += 256) { float v = w[i]; s_wd[i] = make_float2(v, v); }
    if (t < 16) { float v = b[t]; s_bd[t] = make_float2(v, v); }
    if (t < 64) s_aw[t] = aw[t];
    if (t < 4)  s_ab[t] = ab[t];
    __syncthreads();

    int n    = blockIdx.x >> 4;
    int base = (blockIdx.x & 15) * 1024;
    int lane = t & 31, wrp = t >> 5;

    u64t accP = 0ull;   // lane L accumulates reduced value L
    u64t accS = 0ull;   // lane 0 -> asum pair (a0,a1), lane 1 -> (a2,a3)

#pragma unroll 1
    for (int p = 0; p < 4; p++) {
        int pix = base + p * 256 + t;     // 0..16383 within image
        int px = pix & 127;
        int py = pix >> 7;

        int y0 = 2 * py - 1;
        int xc = 2 * px;
        bool left  = (px > 0);
        bool right = (px < 127);

        float xv[16];

        // two sweeps of 8 output channels; channel-outer inside each sweep
#pragma unroll
        for (int sw = 0; sw < 2; sw++) {
            u64t accT[8], accB[8];
#pragma unroll
            for (int o8 = 0; o8 < 8; o8++) {
                accT[o8] = *(const u64t*)&s_bd[sw * 8 + o8];
                accB[o8] = accT[o8];
            }
#pragma unroll
            for (int c = 0; c < 4; c++) {
                u64t prc[4][3];
                const float* xp = g_h1 + ((size_t)(n * 4 + c) << 16);
#pragma unroll
                for (int r = 0; r < 4; r++) {
                    int iy = y0 + r;
                    bool yok = (unsigned)iy < 256u;
                    const float* rp = xp + iy * 256;
                    float2 m = yok ? __ldg((const float2*)(rp + xc))
                                   : make_float2(0.f, 0.f);
                    float v0 = (yok && left)  ? __ldg(rp + xc - 1) : 0.0f;
                    float v3 = (yok && right) ? __ldg(rp + xc + 2) : 0.0f;
                    PACK2(prc[r][0], v0, m.x);
                    PACK2(prc[r][1], m.x, m.y);
                    PACK2(prc[r][2], m.y, v3);
                }
#pragma unroll
                for (int o8 = 0; o8 < 8; o8++) {
                    int oc = sw * 8 + o8;
#pragma unroll
                    for (int ky = 0; ky < 3; ky++)
#pragma unroll
                        for (int kx = 0; kx < 3; kx++) {
                            u64t wd = *(const u64t*)&s_wd[((oc * 4 + c) * 3 + ky) * 3 + kx];
                            FMA2(accT[o8], prc[ky    ][kx], wd);
                            FMA2(accB[o8], prc[ky + 1][kx], wd);
                        }
                }
            }
#pragma unroll
            for (int o8 = 0; o8 < 8; o8++) {
                float a00, a01, a10, a11;
                UNPACK2(a00, a01, accT[o8]);
                UNPACK2(a10, a11, accB[o8]);
                xv[sw * 8 + o8] = 0.25f * (fmaxf(a00, 0.f) + fmaxf(a01, 0.f) +
                                           fmaxf(a10, 0.f) + fmaxf(a11, 0.f));
            }
        }

        // NetVLAD soft-assign for this pixel
        float lg[4];
#pragma unroll
        for (int k = 0; k < 4; k++) {
            float s = s_ab[k];
#pragma unroll
            for (int c = 0; c < 16; c++) s = fmaf(xv[c], s_aw[k * 16 + c], s);
            lg[k] = s;
        }
        float mx = fmaxf(fmaxf(lg[0], lg[1]), fmaxf(lg[2], lg[3]));
        float e0 = __expf(lg[0] - mx), e1 = __expf(lg[1] - mx);
        float e2 = __expf(lg[2] - mx), e3 = __expf(lg[3] - mx);
        float inv = 1.0f / (e0 + e1 + e2 + e3);
        float av[4] = {e0 * inv, e1 * inv, e2 * inv, e3 * inv};

        // V[k*8+j] = (a_k*xv[2j], a_k*xv[2j+1]); pair index p <-> floats 2p,2p+1
        u64t xq[8];
#pragma unroll
        for (int j = 0; j < 8; j++) PACK2(xq[j], xv[2 * j], xv[2 * j + 1]);
        u64t V[32];
#pragma unroll
        for (int k = 0; k < 4; k++) {
            u64t ak2; PACK2(ak2, av[k], av[k]);
#pragma unroll
            for (int j = 0; j < 8; j++) MUL2(V[k * 8 + j], ak2, xq[j]);
        }

        // recursive halving: at level o, keep the half selected by (lane&o),
        // send the other; after 5 levels lane l holds warp-sum of value l.
#pragma unroll
        for (int o = 16; o > 0; o >>= 1) {
#pragma unroll
            for (int j = 0; j < o; j++) {
                bool up = (lane & o) != 0;
                u64t give = up ? V[j] : V[j + o];
                u64t got  = __shfl_xor_sync(0xffffffffu, give, o);
                u64t keep = up ? V[j + o] : V[j];
                ADD2(keep, got);
                V[j] = keep;
            }
        }
        ADD2(accP, V[0]);

        // asum pairs: plain allreduce of 2 packed values
        u64t s01, s23;
        PACK2(s01, av[0], av[1]);
        PACK2(s23, av[2], av[3]);
#pragma unroll
        for (int o = 16; o > 0; o >>= 1) {
            u64t q0 = __shfl_xor_sync(0xffffffffu, s01, o); ADD2(s01, q0);
            u64t q1 = __shfl_xor_sync(0xffffffffu, s23, o); ADD2(s23, q1);
        }
        if (lane == 0) ADD2(accS, s01);
        if (lane == 1) ADD2(accS, s23);
    }

    // per-warp partials -> cross-warp sum -> deterministic chunk partial
    s_red[wrp][lane] = accP;
    if (lane < 2) s_red[wrp][32 + lane] = accS;
    __syncthreads();
    if (t < 34) {
        u64t s = s_red[0][t];
#pragma unroll
        for (int wq = 1; wq < 8; wq++) ADD2(s, s_red[wq][t]);
        g_vpart[blockIdx.x * 34 + t] = s;   // blockIdx.x == n*16 + chunk
    }
}

// ---------------------------------------------------------------------------
// Kernel 3: reduce 16 chunk-partials; vlad[k,c] = acc - asum[k]*cent[k,c];
// intra L2 norm over c; global L2 norm; out = vlad @ lin_w.T + lin_b.
// grid: 32 blocks x 64 threads. g_vpart pair j holds floats (2j, 2j+1):
// j<32 -> vlad[2j],vlad[2j+1]; j=32 -> asum0,asum1; j=33 -> asum2,asum3.
// ---------------------------------------------------------------------------
__global__ void __launch_bounds__(64) k_head(
    const float* __restrict__ cent, const float* __restrict__ lw,
    const float* __restrict__ lb, float* __restrict__ out)
{
    __shared__ float s_v[64];
    __shared__ float s_n[4];
    __shared__ float s_g;
    int n = blockIdx.x, t = threadIdx.x;

    const float* p = (const float*)(g_vpart + (size_t)n * 16 * 34);
    float acc = 0.f, asum = 0.f;
    int k = t >> 4;
#pragma unroll
    for (int s = 0; s < 16; s++) {
        acc  += p[s * 68 + t];
        asum += p[s * 68 + 64 + k];
    }
    float v = acc - asum * cent[t];
    s_v[t] = v;
    __syncthreads();

    if (t < 4) {
        float s = 0.f;
#pragma unroll
        for (int c = 0; c < 16; c++) { float q = s_v[t * 16 + c]; s += q * q; }
        s_n[t] = fmaxf(sqrtf(s), 1e-12f);
    }
    __syncthreads();
    v = s_v[t] / s_n[k];
    s_v[t] = v;
    __syncthreads();
    if (t == 0) {
        float s = 0.f;
#pragma unroll
        for (int i = 0; i < 64; i++) s += s_v[i] * s_v[i];
        s_g = fmaxf(sqrtf(s), 1e-12f);
    }
    __syncthreads();
    if (t < 7) {
        float ig = 1.0f / s_g;
        float s = lb[t];
#pragma unroll
        for (int i = 0; i < 64; i++) s = fmaf(s_v[i] * ig, lw[t * 64 + i], s);
        out[n * 7 + t] = s;
    }
}

// ---------------------------------------------------------------------------
extern "C" void kernel_launch(void* const* d_in, const int* in_sizes, int n_in,
                              void* d_out, int out_size)
{
    const float* x     = (const float*)d_in[0];
    const float* c1w   = (const float*)d_in[1];
    const float* c1b   = (const float*)d_in[2];
    const float* c2w   = (const float*)d_in[3];
    const float* c2b   = (const float*)d_in[4];
    const float* cent  = (const float*)d_in[5];
    const float* aw    = (const float*)d_in[6];
    const float* ab    = (const float*)d_in[7];
    const float* lw    = (const float*)d_in[8];
    const float* lb    = (const float*)d_in[9];
    float* out = (float*)d_out;

    k_conv1<<<NIMG * 256 * 128 / 256, 256>>>(x, c1w, c1b);
    k_conv2_vlad<<<NIMG * 16384 / 1024, 256>>>(c2w, c2b, aw, ab);
    k_head<<<NIMG, 64>>>(cent, lw, lb, out);
}